// round 13
// baseline (speedup 1.0000x reference)
#include <cuda_runtime.h>

// SigmoidFlow: B=2048, D=512, NDIM=16
// out[0..B*D) = xnew ; out[B*D..B*D+B) = logdet
//
// R13 = R12 (2-chunk interleaved body, alu 15%, HBM 5629 GB/s) at 6 CTAs/SM:
// __launch_bounds__(256,6) caps regs at 42 (R11 proved the math fits in 40
// regs single-chunk). Occ 55.5% -> ~72% with MLP 6 if ptxas keeps both
// chunks' loads front-batched. Math: R2 single-rcp cofactor sigmoids,
// 3-log epilogue.

#define TPB 256

__device__ __forceinline__ float fast_rcp(float v) {
    float r; asm("rcp.approx.f32 %0, %1;" : "=f"(r) : "f"(v)); return r;
}

__device__ __forceinline__ void sf_math(float4 av, float4 bv, float4 wv, float xv,
                                        int q, float* __restrict__ op, float& acc)
{
    const float ONE_MD = 1.0f - 1e-6f;
    const float HALF_D = 0.5e-6f;
    const float LOG1MD = -1.0000005e-6f;

    float a_[4] = {av.x, av.y, av.z, av.w};
    float bb[4] = {bv.x, bv.y, bv.z, bv.w};
    float wl[4] = {wv.x, wv.y, wv.z, wv.w};

    float asp[4], t[4], onet[4], ew[4];
    #pragma unroll
    for (int j = 0; j < 4; ++j) {
        float ea  = __expf(a_[j]);
        asp[j]    = __logf(1.0f + ea);            // softplus
        float pre = fmaf(asp[j], xv, bb[j]);
        t[j]      = __expf(-pre);
        onet[j]   = 1.0f + t[j];
        ew[j]     = __expf(wl[j]);
    }
    float p01 = onet[0] * onet[1];
    float p23 = onet[2] * onet[3];
    float iP  = fast_rcp(p01 * p23);
    float h0  = (onet[1] * p23) * iP;
    float h1  = (onet[0] * p23) * iP;
    float h2  = (p01 * onet[3]) * iP;
    float h3  = (p01 * onet[2]) * iP;

    float Wl = (ew[0] + ew[1]) + (ew[2] + ew[3]);
    float Sl = fmaf(ew[3], h3, fmaf(ew[2], h2, fmaf(ew[1], h1, ew[0] * h0)));
    float d0 = (ew[0] * asp[0]) * (t[0] * h0 * h0);
    float d1 = (ew[1] * asp[1]) * (t[1] * h1 * h1);
    float d2 = (ew[2] * asp[2]) * (t[2] * h2 * h2);
    float d3 = (ew[3] * asp[3]) * (t[3] * h3 * h3);
    float Dl = (d0 + d1) + (d2 + d3);

    Wl += __shfl_xor_sync(0xffffffffu, Wl, 1);
    Sl += __shfl_xor_sync(0xffffffffu, Sl, 1);
    Dl += __shfl_xor_sync(0xffffffffu, Dl, 1);
    Wl += __shfl_xor_sync(0xffffffffu, Wl, 2);
    Sl += __shfl_xor_sync(0xffffffffu, Sl, 2);
    Dl += __shfl_xor_sync(0xffffffffu, Dl, 2);

    const float hw = HALF_D * Wl;
    const float N1 = fmaf(ONE_MD, Sl, hw);
    const float N2 = fmaf(ONE_MD, Wl - Sl, hw);
    const float l1 = __logf(N1);
    const float l2 = __logf(N2);
    const float l3 = __logf(Dl * Wl);

    if (q == 0) *op = l1 - l2;                    // xnew
    acc += l3 - l1 - l2 + LOG1MD;                 // replicated x4
}

// Requires D % 128 == 0.
__global__ __launch_bounds__(TPB, 6)
void sf_kernel(const float* __restrict__ x,
               const float* __restrict__ logdet_in,
               const float* __restrict__ dsp,
               float* __restrict__ out,
               int B, int D)
{
    const int b    = blockIdx.x;
    const int tid  = threadIdx.x;
    const int lane = tid & 31;
    const int wid  = tid >> 5;                 // 0..7
    const int q    = lane & 3;
    const int e0   = wid * 8 + (lane >> 2);    // 0..63

    __shared__ float s_part[TPB / 32];

    const float*  xp = x   + (long long)b * D + e0;
    const float4* pp = (const float4*)(dsp + ((long long)b * D + e0) * 48) + q;
    float*        op = out + (long long)b * D + e0;

    float acc = 0.0f;

    const int niter = D >> 7;                  // 128 elements (2 chunks) per iter
    for (int it = 0; it < niter; ++it) {
        // ---- issue ALL loads for both chunks first ----
        const float4 av0 = __ldg(pp);
        const float4 bv0 = __ldg(pp + 4);
        const float4 wv0 = __ldg(pp + 8);
        const float4 av1 = __ldg(pp + 64 * 12);
        const float4 bv1 = __ldg(pp + 64 * 12 + 4);
        const float4 wv1 = __ldg(pp + 64 * 12 + 8);
        const float  xv0 = __ldg(xp);
        const float  xv1 = __ldg(xp + 64);

        // ---- compute both chunks ----
        sf_math(av0, bv0, wv0, xv0, q, op, acc);
        sf_math(av1, bv1, wv1, xv1, q, op + 64, acc);

        pp += 128 * 12;
        xp += 128;
        op += 128;
    }

    // warp + block reduction (each element counted 4x -> scale 0.25)
    #pragma unroll
    for (int m = 16; m >= 1; m >>= 1)
        acc += __shfl_xor_sync(0xffffffffu, acc, m);
    if (lane == 0) s_part[wid] = acc;
    __syncthreads();

    if (wid == 0) {
        float v = (lane < (TPB / 32)) ? s_part[lane] : 0.0f;
        #pragma unroll
        for (int m = 4; m >= 1; m >>= 1)
            v += __shfl_xor_sync(0xffffffffu, v, m);
        if (lane == 0)
            out[(long long)B * D + b] = 0.25f * v + __ldg(logdet_in + b);
    }
}

// Generic fallback for D not a multiple of 128.
__global__ __launch_bounds__(TPB)
void sf_kernel_gen(const float* __restrict__ x,
                   const float* __restrict__ logdet_in,
                   const float* __restrict__ dsp,
                   float* __restrict__ out,
                   int B, int D)
{
    const int b    = blockIdx.x;
    const int tid  = threadIdx.x;
    const int lane = tid & 31;
    const int wid  = tid >> 5;
    const int q    = lane & 3;
    const int e0   = wid * 8 + (lane >> 2);

    __shared__ float s_part[TPB / 32];
    float acc = 0.0f;

    const int niter = (D + 63) / 64;
    for (int it = 0; it < niter; ++it) {
        const int d = it * 64 + e0;
        if (d < D) {
            const long long idx = (long long)b * D + d;
            const float4* p = (const float4*)(dsp + idx * 48);
            sf_math(__ldg(p + q), __ldg(p + 4 + q), __ldg(p + 8 + q),
                    __ldg(x + idx), q, out + idx, acc);
        }
    }

    #pragma unroll
    for (int m = 16; m >= 1; m >>= 1)
        acc += __shfl_xor_sync(0xffffffffu, acc, m);
    if (lane == 0) s_part[wid] = acc;
    __syncthreads();

    if (wid == 0) {
        float v = (lane < (TPB / 32)) ? s_part[lane] : 0.0f;
        #pragma unroll
        for (int m = 4; m >= 1; m >>= 1)
            v += __shfl_xor_sync(0xffffffffu, v, m);
        if (lane == 0)
            out[(long long)B * D + b] = 0.25f * v + __ldg(logdet_in + b);
    }
}

extern "C" void kernel_launch(void* const* d_in, const int* in_sizes, int n_in,
                              void* d_out, int out_size)
{
    const float* x   = (const float*)d_in[0];   // (B, D)
    const float* ld  = (const float*)d_in[1];   // (B,)
    const float* dsp = (const float*)d_in[2];   // (B, D, 48)
    float* out = (float*)d_out;

    const int B = in_sizes[1];
    const int D = in_sizes[0] / B;

    if ((D & 127) == 0)
        sf_kernel<<<B, TPB>>>(x, ld, dsp, out, B, D);
    else
        sf_kernel_gen<<<B, TPB>>>(x, ld, dsp, out, B, D);
}

// round 14
// speedup vs baseline: 1.0520x; 1.0520x over previous
#include <cuda_runtime.h>

// SigmoidFlow: B=2048, D=512, NDIM=16
// out[0 .. B*D)      = xnew
// out[B*D .. B*D+B)  = logdet
//
// FINAL: the profiled-best configuration of the session (ncu 37.50us,
// HBM 5654 GB/s = 99% of the measured ~5.65 TB/s streaming ceiling for this
// 192B-strided read pattern; required traffic ~210MB is irreducible).
// TPB=512, one row per CTA, 4 lanes per element (3x LDG.128/thread, 100%
// sector utilization), plain cache policy.
//
// Key identity: exp(log_softmax(wl)_k + logsig(pre) + logsig(-pre) + log a_k)
//             = (e^{wl_k}/W) * a_k * sigm_k * (1-sigm_k)
// so logsumexp over k = log(sum_k e^{wl_k} a_k t r^2) - log(W), with
// t = exp(-pre), r = 1/(1+t) = sigm.

#define TPB 512

__global__ __launch_bounds__(TPB)
void sigmoid_flow_kernel(const float* __restrict__ x,
                         const float* __restrict__ logdet_in,
                         const float* __restrict__ dsp,
                         float* __restrict__ out,
                         int B, int D)
{
    const int b    = blockIdx.x;
    const int tid  = threadIdx.x;
    const int lane = tid & 31;
    const int wid  = tid >> 5;          // 0..15
    const int q    = lane & 3;          // component-group within element
    const int esub = lane >> 2;         // 0..7 element within warp
    const int e_in_block = wid * 8 + esub;   // 0..127

    const float ONE_MD  = 1.0f - 1e-6f;
    const float HALF_D  = 0.5e-6f;
    const float LOG1MD  = -1.0000005e-6f;   // log(1-1e-6)

    __shared__ float s_part[TPB / 32];

    float acc = 0.0f;   // per-thread logdet partial (each element counted 4x)

    const int niter = (D + 127) / 128;
    for (int it = 0; it < niter; ++it) {
        const int d = it * 128 + e_in_block;
        if (d < D) {
            const long long idx = (long long)b * D + d;
            // dsparams row: 48 floats = 12 float4, 16B-aligned (idx*192 bytes)
            const float4* p = (const float4*)(dsp + idx * 48);
            const float4 av = p[q];        // a_  components 4q..4q+3
            const float4 bv = p[4 + q];    // b_
            const float4 wv = p[8 + q];    // w_logits
            const float xv = __ldg(x + idx);

            float sumw = 0.0f, sums = 0.0f, sumd = 0.0f;

            #pragma unroll
            for (int j = 0; j < 4; ++j) {
                const float a_ = (j == 0) ? av.x : (j == 1) ? av.y : (j == 2) ? av.z : av.w;
                const float bb = (j == 0) ? bv.x : (j == 1) ? bv.y : (j == 2) ? bv.z : bv.w;
                const float wl = (j == 0) ? wv.x : (j == 1) ? wv.y : (j == 2) ? wv.z : wv.w;

                const float ea  = __expf(a_);
                const float a   = __logf(1.0f + ea);        // softplus(a_)
                const float pre = fmaf(a, xv, bb);
                const float t   = __expf(-pre);             // safe: |pre| << 88
                const float r   = __fdividef(1.0f, 1.0f + t);   // sigm
                const float ew  = __expf(wl);               // unnormalized softmax

                sumw += ew;
                sums += ew * r;                              // ew * sigm
                sumd  = fmaf(ew * a, t * r * r, sumd);       // ew * a * sigm*(1-sigm)
            }

            // reduce the 3 sums across the 4-lane group (xor 1, xor 2)
            sumw += __shfl_xor_sync(0xffffffffu, sumw, 1);
            sums += __shfl_xor_sync(0xffffffffu, sums, 1);
            sumd += __shfl_xor_sync(0xffffffffu, sumd, 1);
            sumw += __shfl_xor_sync(0xffffffffu, sumw, 2);
            sums += __shfl_xor_sync(0xffffffffu, sums, 2);
            sumd += __shfl_xor_sync(0xffffffffu, sumd, 2);

            const float invW = __fdividef(1.0f, sumw);
            const float xpre = sums * invW;
            const float xpc  = fmaf(xpre, ONE_MD, HALF_D);
            const float lx   = __logf(xpc);
            const float l1x  = __logf(1.0f - xpc);

            if (q == 0) out[idx] = lx - l1x;                 // xnew

            const float logj = __logf(sumd * invW);          // logsumexp(logj_k)
            acc += logj + LOG1MD - lx - l1x;                 // replicated on 4 lanes
        }
    }

    // warp reduction (each element counted 4x -> scale by 0.25 at the end)
    #pragma unroll
    for (int m = 16; m >= 1; m >>= 1)
        acc += __shfl_xor_sync(0xffffffffu, acc, m);
    if (lane == 0) s_part[wid] = acc;
    __syncthreads();

    if (wid == 0) {
        float v = (lane < (TPB / 32)) ? s_part[lane] : 0.0f;
        #pragma unroll
        for (int m = 8; m >= 1; m >>= 1)
            v += __shfl_xor_sync(0xffffffffu, v, m);
        if (lane == 0)
            out[(long long)B * D + b] = 0.25f * v + __ldg(logdet_in + b);
    }
}

extern "C" void kernel_launch(void* const* d_in, const int* in_sizes, int n_in,
                              void* d_out, int out_size)
{
    const float* x   = (const float*)d_in[0];   // (B, D)
    const float* ld  = (const float*)d_in[1];   // (B,)
    const float* dsp = (const float*)d_in[2];   // (B, D, 48)
    float* out = (float*)d_out;

    const int B = in_sizes[1];
    const int D = in_sizes[0] / B;

    sigmoid_flow_kernel<<<B, TPB>>>(x, ld, dsp, out, B, D);
}